// round 5
// baseline (speedup 1.0000x reference)
#include <cuda_runtime.h>

// DILATE loss — band-wavefront soft-DTW fwd+bwd, TWO batches per CTA interleaved
// in registers (dual independent DP chains per warp hide each other's latency).
// grid = 128 CTAs (one per SM, single balanced wave). Base-2 math; min/median/max
// softmin network (one exp is free). Points packed as float4 pairs, stride 12.

#define NB    256
#define NN    336
#define NV    7
#define ND    673
#define DS    352
#define TPB   352
#define NW    11
#define BNDW  344
#define PSTR  12               // padded floats per point (2 x float4 used, conflict-free)
#define LOG2E 1.4426950408889634f
#define LN2   0.6931471805599453f
#define BIG2  1.442695e8f
#define NEGS  -1.0e30f
#define PF    8
#define FULLM 0xffffffffu

__device__ float    g_R[(size_t)NB * ND * DS];
__device__ double   g_shape_acc;
__device__ double   g_temp_acc;
__device__ unsigned g_done;

static __device__ __forceinline__ float ex2f(float x) {
    float r; asm("ex2.approx.f32 %0, %1;" : "=f"(r) : "f"(x)); return r;
}
static __device__ __forceinline__ float lg2f(float x) {
    float r; asm("lg2.approx.f32 %0, %1;" : "=f"(r) : "f"(x)); return r;
}

extern __shared__ float smem[];

__global__ __launch_bounds__(TPB, 1)
void dilate_kernel(const float* __restrict__ outputs,
                   const float* __restrict__ targets,
                   float* __restrict__ out) {
    const int tid = threadIdx.x;
    const int w   = tid >> 5;
    const int l   = tid & 31;
    const int i   = 32 * w + l + 1;
    const bool row_ok = (i <= NN);

    // dynamic smem layout
    float* o4   = smem;                       // [u][j][PSTR]
    float* bndA = o4 + 2 * NN * PSTR;         // [u][w][BNDW]
    float* bndB = bndA + 2 * NW * BNDW;       // [u][w][BNDW]
    __shared__ float warpsum[NW];
    __shared__ float shape_s[2];

    float* gRb[2];
    const float* obs[2];
    const float* tbs[2];
#pragma unroll
    for (int u = 0; u < 2; u++) {
        int b = 2 * blockIdx.x + u;
        gRb[u] = g_R + (size_t)b * ND * DS;
        obs[u] = outputs + (size_t)b * NN * NV;
        tbs[u] = targets + (size_t)b * NN * NV;
    }

    // load points: [j][PSTR] with slots 0..6 = dims, 7 = ||o_j||^2
#pragma unroll
    for (int u = 0; u < 2; u++) {
        float* ou = o4 + u * NN * PSTR;
        for (int k = tid; k < NN * NV; k += TPB) {
            int j = k / NV, v = k - j * NV;
            ou[j * PSTR + v] = obs[u][k];
        }
    }
    __syncthreads();
#pragma unroll
    for (int u = 0; u < 2; u++) {
        float* ou = o4 + u * NN * PSTR;
        for (int j = tid; j < NN; j += TPB) {
            float s = 0.f;
#pragma unroll
            for (int v = 0; v < NV; v++) { float x = ou[j * PSTR + v]; s = fmaf(x, x, s); }
            ou[j * PSTR + 7] = s;
        }
    }
    float tr[2][NV], tn[2];
#pragma unroll
    for (int u = 0; u < 2; u++) {
        tn[u] = 0.f;
        if (row_ok) {
#pragma unroll
            for (int v = 0; v < NV; v++) {
                tr[u][v] = tbs[u][(i - 1) * NV + v];
                tn[u] = fmaf(tr[u][v], tr[u][v], tn[u]);
            }
        }
    }
    // forward boundary prefill
#pragma unroll
    for (int u = 0; u < 2; u++) {
        float* bA = bndA + u * NW * BNDW;
        for (int k = tid; k < BNDW; k += TPB) bA[k] = (k == 0) ? 0.f : BIG2;
        if (tid > 0 && tid < NW) bA[tid * BNDW] = BIG2;
    }
    if (tid < 2) shape_s[tid] = 0.f;
    __syncthreads();

    // ================= forward =================
    {
        float Rprev[2] = {BIG2, BIG2}, upc[2] = {BIG2, BIG2},
              upp[2]  = {BIG2, BIG2}, prevB[2];
        const int off = 64 * w;
        const int pstart = off >> 5, pend = (off + 366) >> 5;
        for (int p = 0; p < 31; p++) {
            if (p >= pstart && p <= pend) {
                if (p == pstart && l == 0) {
#pragma unroll
                    for (int u = 0; u < 2; u++) prevB[u] = bndA[u * NW * BNDW + w * BNDW];
                }
                int s = p << 5;
#pragma unroll 4
                for (int k = 0; k < 32; k++, s++) {
                    int j = s - off - l + 1;
                    bool act = row_ok && (j >= 1) && (j <= NN);
                    int jm = min(max(j - 1, 0), NN - 1);
                    int jc = min(max(j, 0), BNDW - 1);
#pragma unroll
                    for (int u = 0; u < 2; u++) {
                        const float4 a = *(const float4*)(o4 + (u * NN + jm) * PSTR);
                        const float4 c = *(const float4*)(o4 + (u * NN + jm) * PSTR + 4);
                        float dot = tr[u][0] * a.x;
                        dot = fmaf(tr[u][1], a.y, dot);
                        dot = fmaf(tr[u][2], a.z, dot);
                        dot = fmaf(tr[u][3], a.w, dot);
                        dot = fmaf(tr[u][4], c.x, dot);
                        dot = fmaf(tr[u][5], c.y, dot);
                        dot = fmaf(tr[u][6], c.z, dot);
                        float D2 = fmaxf(fmaf(-2.f, dot, tn[u] + c.w), 0.f) * LOG2E;
                        float ru = upc[u], rd = upp[u], curB = 0.f;
                        if (l == 0) {
                            curB = bndA[u * NW * BNDW + w * BNDW + jc];
                            ru = curB; rd = prevB[u];
                        }
                        float rl = Rprev[u];
                        float lo = fminf(rd, ru), hi = fmaxf(rd, ru);
                        float m  = fminf(lo, rl);
                        float md = fmaxf(lo, fminf(hi, rl));
                        float Mx = fmaxf(hi, rl);
                        float z  = 1.f + ex2f(m - md) + ex2f(m - Mx);
                        float Rn = D2 + m - lg2f(z);
                        Rn = act ? Rn : BIG2;
                        if (act) {
                            gRb[u][(size_t)(s - 32 * w + 2) * DS + i] = Rn;
                            if (l == 31 && w < NW - 1) bndA[u * NW * BNDW + (w + 1) * BNDW + j] = Rn;
                        }
                        float sh = __shfl_up_sync(FULLM, Rn, 1);
                        upp[u] = upc[u]; upc[u] = sh;
                        if (l == 0) prevB[u] = curB;
                        Rprev[u] = Rn;
                    }
                }
            }
            __syncthreads();
        }
    }

    // re-init boundaries for backward
    for (int k = tid; k < 2 * NW * BNDW; k += TPB) { bndA[k] = 0.f; bndB[k] = NEGS; }
    __syncthreads();

    // ================= backward =================
    float acc = 0.f;
    {
        float Eprev[2] = {0.f, 0.f}, Sprev[2] = {NEGS, NEGS};
        float Edn1[2]  = {0.f, 0.f}, Sdn1[2]  = {NEGS, NEGS};
        float Edn2[2]  = {0.f, 0.f}, Sdn2[2]  = {NEGS, NEGS};
        float rring[2][PF];
        const int off = 64 * (10 - w);
        const int pstart = off >> 5, pend = (off + 366) >> 5;
        const int irow = min(i, DS - 1);
        for (int p = 0; p < 32; p++) {
            if (p >= pstart && p <= pend) {
                int s0 = p << 5;
                if (p == pstart) {
#pragma unroll
                    for (int q = 0; q < PF; q++) {
                        int d = 1008 - 32 * w - (s0 + q);
                        d = min(max(d, 0), ND - 1);
#pragma unroll
                        for (int u = 0; u < 2; u++)
                            rring[u][(s0 + q) & (PF - 1)] = gRb[u][(size_t)d * DS + irow];
                    }
                }
                int s = s0;
#pragma unroll 4
                for (int kk = 0; kk < 32; kk++, s++) {
                    int j = 367 + off - s - l;
                    bool act = row_ok && (j >= 1) && (j <= NN);
                    int jm = min(max(j - 1, 0), NN - 1);
                    int jc = min(max(j, 0), BNDW - 1);
                    int dpf = 1008 - 32 * w - (s + PF);
                    dpf = min(max(dpf, 0), ND - 1);
                    int slot = s & (PF - 1);
#pragma unroll
                    for (int u = 0; u < 2; u++) {
                        float Rij = rring[u][slot];
                        rring[u][slot] = gRb[u][(size_t)dpf * DS + irow];
                        if (l == 31) {
                            Edn1[u] = bndA[u * NW * BNDW + w * BNDW + jc];
                            Sdn1[u] = bndB[u * NW * BNDW + w * BNDW + jc];
                        }
                        const float4 a = *(const float4*)(o4 + (u * NN + jm) * PSTR);
                        const float4 c = *(const float4*)(o4 + (u * NN + jm) * PSTR + 4);
                        float dot = tr[u][0] * a.x;
                        dot = fmaf(tr[u][1], a.y, dot);
                        dot = fmaf(tr[u][2], a.z, dot);
                        dot = fmaf(tr[u][3], a.w, dot);
                        dot = fmaf(tr[u][4], c.x, dot);
                        dot = fmaf(tr[u][5], c.y, dot);
                        dot = fmaf(tr[u][6], c.z, dot);
                        float D2 = fmaxf(fmaf(-2.f, dot, tn[u] + c.w), 0.f) * LOG2E;
                        float w1 = ex2f(Sdn1[u] - Rij);
                        float w2 = ex2f(Sprev[u] - Rij);
                        float w3 = ex2f(Sdn2[u] - Rij);
                        float En = Edn1[u] * w1 + Eprev[u] * w2 + Edn2[u] * w3;
                        if (i == NN && j == NN) { En = 1.f; shape_s[u] = Rij * LN2; }
                        float Sn = Rij - D2;
                        En = act ? En : 0.f;
                        Sn = act ? Sn : NEGS;
                        if (act) {
                            float df = (float)(i - j);
                            acc = fmaf(En, df * df, acc);
                            if (l == 0 && w > 0) {
                                bndA[u * NW * BNDW + (w - 1) * BNDW + j] = En;
                                bndB[u * NW * BNDW + (w - 1) * BNDW + j] = Sn;
                            }
                        }
                        float Es = __shfl_down_sync(FULLM, En, 1);
                        float Ss = __shfl_down_sync(FULLM, Sn, 1);
                        Edn2[u] = Edn1[u]; Sdn2[u] = Sdn1[u];
                        Edn1[u] = Es;      Sdn1[u] = Ss;
                        Eprev[u] = En;     Sprev[u] = Sn;
                    }
                }
            }
            __syncthreads();
        }
    }

    // ------- reduce temporal accumulator, finalize in last CTA -------
#pragma unroll
    for (int o2 = 16; o2; o2 >>= 1) acc += __shfl_down_sync(FULLM, acc, o2);
    if (l == 0) warpsum[w] = acc;
    __syncthreads();
    if (tid == 0) {
        float sum = 0.f;
#pragma unroll
        for (int q = 0; q < NW; q++) sum += warpsum[q];
        atomicAdd(&g_temp_acc, (double)sum);
        atomicAdd(&g_shape_acc, (double)shape_s[0] + (double)shape_s[1]);
        __threadfence();
        unsigned old = atomicAdd(&g_done, 1u);
        if (old == (NB / 2) - 1) {
            __threadfence();
            double shape    = g_shape_acc / (double)NB;
            double temporal = g_temp_acc / ((double)NN * NN * NB * NB);
            out[0] = (float)(0.5 * shape + 0.5 * temporal);
            g_shape_acc = 0.0;
            g_temp_acc  = 0.0;
            __threadfence();
            g_done = 0u;
        }
    }
}

extern "C" void kernel_launch(void* const* d_in, const int* in_sizes, int n_in,
                              void* d_out, int out_size) {
    const float* outputs = (const float*)d_in[0];
    const float* targets = (const float*)d_in[1];
    static int smem_set = 0;
    int smem_bytes = (2 * NN * PSTR + 4 * NW * BNDW) * sizeof(float);
    if (!smem_set) {
        cudaFuncSetAttribute(dilate_kernel, cudaFuncAttributeMaxDynamicSharedMemorySize,
                             smem_bytes);
        smem_set = 1;
    }
    dilate_kernel<<<NB / 2, TPB, smem_bytes>>>(outputs, targets, (float*)d_out);
}

// round 7
// speedup vs baseline: 3.9763x; 3.9763x over previous
#include <cuda_runtime.h>

// DILATE loss — band-wavefront soft-DTW fwd+bwd, one CTA per batch (grid 256).
// Warp w owns rows 32w+1..32w+32, lanes column-staggered, intra-warp deps via shfl,
// cross-band boundary via smem (64-col skew), barrier per 32 steps. Base-2 math.
// Padded smem (width 512) and padded g_R remove all index clamps from the hot loops.
// Backward re-reads R via a 16-deep statically-indexed register prefetch ring.
// R6 bugfix: boundary prefill writes R[0][0]=0 inside the strided fill (race-free).

#define NB    256
#define NN    336
#define NV    7
#define ND    673
#define DS    352
#define TPB   352
#define NW    11
#define W2    512            // padded width for smem arrays
#define PADJ  64             // front pad for j-indexing
#define LOG2E 1.4426950408889634f
#define LN2   0.6931471805599453f
#define BIG2  1.442695e8f
#define NEGS  -1.0e30f
#define PF    16
#define FULLM 0xffffffffu

// g_R padded by 32 diagonals front and 64 back (garbage reads from out-of-window lanes)
__device__ float    g_R[((size_t)NB * ND + 96) * DS];
__device__ double   g_shape_acc;
__device__ double   g_temp_acc;
__device__ unsigned g_done;

static __device__ __forceinline__ float ex2f(float x) {
    float r; asm("ex2.approx.f32 %0, %1;" : "=f"(r) : "f"(x)); return r;
}
static __device__ __forceinline__ float lg2f(float x) {
    float r; asm("lg2.approx.f32 %0, %1;" : "=f"(r) : "f"(x)); return r;
}

extern __shared__ float smem[];

__global__ __launch_bounds__(TPB, 2)
void dilate_kernel(const float* __restrict__ outputs,
                   const float* __restrict__ targets,
                   float* __restrict__ out) {
    const int b   = blockIdx.x;
    const int tid = threadIdx.x;
    const int w   = tid >> 5;
    const int l   = tid & 31;
    const int i   = 32 * w + l + 1;
    const bool row_ok = (i <= NN);

    float* o_s  = smem;                    // [v][W2], v<7 dims at slot j-1+PADJ; [7]=log2e*||o||^2
    float* bndA = o_s + 8 * W2;            // [NW][W2]
    float* bndB = bndA + NW * W2;          // [NW][W2]
    __shared__ float warpsum[NW];
    __shared__ float shape_s;

    const float* ob = outputs + (size_t)b * NN * NV;
    const float* tb = targets + (size_t)b * NN * NV;

    // zero-fill padded point arrays, then load transposed
    for (int k = tid; k < 8 * W2; k += TPB) o_s[k] = 0.f;
    __syncthreads();
    for (int k = tid; k < NN * NV; k += TPB) {
        int j = k / NV, v = k - j * NV;
        o_s[v * W2 + j + PADJ] = ob[k];
    }
    __syncthreads();
    for (int j = tid; j < NN; j += TPB) {
        float s = 0.f;
#pragma unroll
        for (int v = 0; v < NV; v++) { float x = o_s[v * W2 + j + PADJ]; s = fmaf(x, x, s); }
        o_s[7 * W2 + j + PADJ] = s * LOG2E;
    }
    float tL[NV], tn2 = 0.f;
    if (row_ok) {
        float tnr = 0.f;
#pragma unroll
        for (int v = 0; v < NV; v++) {
            float tv = tb[(i - 1) * NV + v];
            tnr = fmaf(tv, tv, tnr);
            tL[v] = 2.f * LOG2E * tv;
        }
        tn2 = tnr * LOG2E;
    } else {
#pragma unroll
        for (int v = 0; v < NV; v++) tL[v] = 0.f;
    }
    // forward boundary prefill: everything BIG2, except R[0][0] = 0 (race-free:
    // the zero is produced by the same strided fill, not a separate write)
    for (int k = tid; k < NW * W2; k += TPB) bndA[k] = (k == PADJ) ? 0.f : BIG2;
    if (tid == 0) shape_s = 0.f;
    __syncthreads();

    float* gRb = g_R + 32 * (size_t)DS + (size_t)b * ND * DS;

    // ================= forward =================
    {
        float Rprev = BIG2, upc = BIG2, upp = BIG2, prevB = BIG2;
        const int off = 64 * w;
        const int pstart = off >> 5, pend = (off + 366) >> 5;
        const float* bArow = bndA + w * W2 + PADJ;
        float* bAnext = bndA + (w + 1) * W2 + PADJ;
        for (int p = 0; p < 31; p++) {
            if (p >= pstart && p <= pend) {
                int s0 = p << 5;
                int j = s0 - off - l + 1;
                if (p == pstart && l == 0) prevB = bArow[0];
                float* gptr = gRb + (size_t)(s0 - 32 * w + 2) * DS + i;
#pragma unroll 8
                for (int k = 0; k < 32; k++) {
                    bool act = row_ok && ((unsigned)(j - 1) < (unsigned)NN);
                    const float* oj = o_s + (j - 1 + PADJ);
                    float acc0 = tn2 + oj[7 * W2];
                    acc0 = fmaf(-tL[0], oj[0 * W2], acc0);
                    acc0 = fmaf(-tL[1], oj[1 * W2], acc0);
                    acc0 = fmaf(-tL[2], oj[2 * W2], acc0);
                    acc0 = fmaf(-tL[3], oj[3 * W2], acc0);
                    acc0 = fmaf(-tL[4], oj[4 * W2], acc0);
                    acc0 = fmaf(-tL[5], oj[5 * W2], acc0);
                    acc0 = fmaf(-tL[6], oj[6 * W2], acc0);
                    float D2 = fmaxf(acc0, 0.f);
                    float ru = upc, rd = upp, curB = 0.f;
                    if (l == 0) { curB = bArow[j]; ru = curB; rd = prevB; }
                    float rl = Rprev;
                    float lo = fminf(rd, ru), hi = fmaxf(rd, ru);
                    float m  = fminf(lo, rl);
                    float md = fmaxf(lo, fminf(hi, rl));
                    float Mx = fmaxf(hi, rl);
                    float z  = 1.f + ex2f(m - md) + ex2f(m - Mx);
                    float Rn = D2 + m - lg2f(z);
                    Rn = act ? Rn : BIG2;
                    if (act) {
                        *gptr = Rn;
                        if (l == 31 && w < NW - 1) bAnext[j] = Rn;
                    }
                    float sh = __shfl_up_sync(FULLM, Rn, 1);
                    upp = upc; upc = sh;
                    if (l == 0) prevB = curB;
                    Rprev = Rn;
                    j++; gptr += DS;
                }
            }
            __syncthreads();
        }
    }

    // re-init boundaries for backward: E = 0, s = NEGS
    for (int k = tid; k < NW * W2; k += TPB) { bndA[k] = 0.f; bndB[k] = NEGS; }
    __syncthreads();

    // ================= backward =================
    float tacc = 0.f;
    {
        float Eprev = 0.f, Sprev = NEGS;
        float Edn1  = 0.f, Sdn1  = NEGS;
        float Edn2  = 0.f, Sdn2  = NEGS;
        float rring[PF];
        const int off = 64 * (10 - w);
        const int pstart = off >> 5, pend = (off + 366) >> 5;
        const float* bArow = bndA + w * W2 + PADJ;
        const float* bBrow = bndB + w * W2 + PADJ;
        float* bAprev = bndA + (w - 1) * W2 + PADJ;
        float* bBprev = bndB + (w - 1) * W2 + PADJ;
        const bool seed_lane = (i == NN);
        for (int p = 0; p < 32; p++) {
            if (p >= pstart && p <= pend) {
                int s0 = p << 5;
                if (p == pstart) {
                    const float* pr = gRb + (size_t)(1008 - 32 * w - s0) * DS + i;
#pragma unroll
                    for (int q = 0; q < PF; q++) { rring[q] = *pr; pr -= DS; }
                }
                int j = 367 + off - s0 - l;
                float df = (float)(i - j);
                const float* ppf = gRb + (size_t)(1008 - 32 * w - s0 - PF) * DS + i;
#pragma unroll 2
                for (int kb = 0; kb < 2; kb++) {
#pragma unroll
                    for (int kk = 0; kk < PF; kk++) {
                        bool act = row_ok && ((unsigned)(j - 1) < (unsigned)NN);
                        float Rij = rring[kk];
                        rring[kk] = *ppf; ppf -= DS;
                        if (l == 31) { Edn1 = bArow[j]; Sdn1 = bBrow[j]; }
                        const float* oj = o_s + (j - 1 + PADJ);
                        float acc0 = tn2 + oj[7 * W2];
                        acc0 = fmaf(-tL[0], oj[0 * W2], acc0);
                        acc0 = fmaf(-tL[1], oj[1 * W2], acc0);
                        acc0 = fmaf(-tL[2], oj[2 * W2], acc0);
                        acc0 = fmaf(-tL[3], oj[3 * W2], acc0);
                        acc0 = fmaf(-tL[4], oj[4 * W2], acc0);
                        acc0 = fmaf(-tL[5], oj[5 * W2], acc0);
                        acc0 = fmaf(-tL[6], oj[6 * W2], acc0);
                        float D2 = fmaxf(acc0, 0.f);
                        float w1 = ex2f(Sdn1 - Rij);
                        float w2 = ex2f(Sprev - Rij);
                        float w3 = ex2f(Sdn2 - Rij);
                        float En = fmaf(Edn1, w1, fmaf(Eprev, w2, Edn2 * w3));
                        if (seed_lane && j == NN) { En = 1.f; shape_s = Rij * LN2; }
                        float Sn = Rij - D2;
                        En = act ? En : 0.f;
                        Sn = act ? Sn : NEGS;
                        tacc = fmaf(En, df * df, tacc);
                        if (act && l == 0 && w > 0) { bAprev[j] = En; bBprev[j] = Sn; }
                        float Es = __shfl_down_sync(FULLM, En, 1);
                        float Ss = __shfl_down_sync(FULLM, Sn, 1);
                        Edn2 = Edn1; Sdn2 = Sdn1;
                        Edn1 = Es;   Sdn1 = Ss;
                        Eprev = En;  Sprev = Sn;
                        j--; df += 1.f;
                    }
                }
            }
            __syncthreads();
        }
    }

    // ------- reduce temporal accumulator, finalize in last CTA -------
#pragma unroll
    for (int o2 = 16; o2; o2 >>= 1) tacc += __shfl_down_sync(FULLM, tacc, o2);
    if (l == 0) warpsum[w] = tacc;
    __syncthreads();
    if (tid == 0) {
        float sum = 0.f;
#pragma unroll
        for (int q = 0; q < NW; q++) sum += warpsum[q];
        atomicAdd(&g_temp_acc, (double)sum);
        atomicAdd(&g_shape_acc, (double)shape_s);
        __threadfence();
        unsigned old = atomicAdd(&g_done, 1u);
        if (old == NB - 1) {
            __threadfence();
            double shape    = g_shape_acc / (double)NB;
            double temporal = g_temp_acc / ((double)NN * NN * NB * NB);
            out[0] = (float)(0.5 * shape + 0.5 * temporal);
            g_shape_acc = 0.0;
            g_temp_acc  = 0.0;
            __threadfence();
            g_done = 0u;
        }
    }
}

extern "C" void kernel_launch(void* const* d_in, const int* in_sizes, int n_in,
                              void* d_out, int out_size) {
    const float* outputs = (const float*)d_in[0];
    const float* targets = (const float*)d_in[1];
    static int smem_set = 0;
    int smem_bytes = (8 * W2 + 2 * NW * W2) * sizeof(float);   // 61440 B
    if (!smem_set) {
        cudaFuncSetAttribute(dilate_kernel, cudaFuncAttributeMaxDynamicSharedMemorySize,
                             smem_bytes);
        smem_set = 1;
    }
    dilate_kernel<<<NB, TPB, smem_bytes>>>(outputs, targets, (float*)d_out);
}

// round 8
// speedup vs baseline: 4.0306x; 1.0137x over previous
#include <cuda_runtime.h>

// DILATE loss — band-wavefront soft-DTW fwd+bwd, one CTA per batch (grid 256).
// Warp w owns rows 32w+1..32w+32, lanes column-staggered, intra-warp deps via shfl,
// cross-band boundary via smem (64-col skew), barrier per 32 steps. Base-2 math.
// R8: points packed [j][12] so D-recompute is 2x LDS.128 (conflict-free, stride 12)
// instead of 8 scalar LDS; point pointer stepped +-48B per cell.

#define NB    256
#define NN    336
#define NV    7
#define ND    673
#define DS    352
#define TPB   352
#define NW    11
#define W2    512            // padded width for boundary arrays
#define PADJ  64             // front pad for j-indexing
#define PSTR  12             // floats per packed point (2 x float4 used)
#define NPTS  (NN + 2*PADJ)  // 464 padded points
#define LOG2E 1.4426950408889634f
#define LN2   0.6931471805599453f
#define BIG2  1.442695e8f
#define NEGS  -1.0e30f
#define PF    16
#define FULLM 0xffffffffu

// g_R padded by 32 diagonals front and 64 back (garbage reads from out-of-window lanes)
__device__ float    g_R[((size_t)NB * ND + 96) * DS];
__device__ double   g_shape_acc;
__device__ double   g_temp_acc;
__device__ unsigned g_done;

static __device__ __forceinline__ float ex2f(float x) {
    float r; asm("ex2.approx.f32 %0, %1;" : "=f"(r) : "f"(x)); return r;
}
static __device__ __forceinline__ float lg2f(float x) {
    float r; asm("lg2.approx.f32 %0, %1;" : "=f"(r) : "f"(x)); return r;
}

extern __shared__ float smem[];

__global__ __launch_bounds__(TPB, 2)
void dilate_kernel(const float* __restrict__ outputs,
                   const float* __restrict__ targets,
                   float* __restrict__ out) {
    const int b   = blockIdx.x;
    const int tid = threadIdx.x;
    const int w   = tid >> 5;
    const int l   = tid & 31;
    const int i   = 32 * w + l + 1;
    const bool row_ok = (i <= NN);

    float* opack = smem;                     // [NPTS][PSTR]: 0-6 dims, 7 = log2e*||o||^2
    float* bndA  = opack + NPTS * PSTR;      // [NW][W2]
    float* bndB  = bndA + NW * W2;           // [NW][W2]
    __shared__ float warpsum[NW];
    __shared__ float shape_s;

    const float* ob = outputs + (size_t)b * NN * NV;
    const float* tb = targets + (size_t)b * NN * NV;

    // zero-fill padded point array, then load transposed
    for (int k = tid; k < NPTS * PSTR; k += TPB) opack[k] = 0.f;
    __syncthreads();
    for (int k = tid; k < NN * NV; k += TPB) {
        int j = k / NV, v = k - j * NV;
        opack[(j + PADJ) * PSTR + v] = ob[k];
    }
    __syncthreads();
    for (int j = tid; j < NN; j += TPB) {
        float s = 0.f;
#pragma unroll
        for (int v = 0; v < NV; v++) { float x = opack[(j + PADJ) * PSTR + v]; s = fmaf(x, x, s); }
        opack[(j + PADJ) * PSTR + 7] = s * LOG2E;
    }
    float tL[NV], tn2 = 0.f;
    if (row_ok) {
        float tnr = 0.f;
#pragma unroll
        for (int v = 0; v < NV; v++) {
            float tv = tb[(i - 1) * NV + v];
            tnr = fmaf(tv, tv, tnr);
            tL[v] = 2.f * LOG2E * tv;
        }
        tn2 = tnr * LOG2E;
    } else {
#pragma unroll
        for (int v = 0; v < NV; v++) tL[v] = 0.f;
    }
    // forward boundary prefill: everything BIG2, except R[0][0] = 0 (race-free)
    for (int k = tid; k < NW * W2; k += TPB) bndA[k] = (k == PADJ) ? 0.f : BIG2;
    if (tid == 0) shape_s = 0.f;
    __syncthreads();

    float* gRb = g_R + 32 * (size_t)DS + (size_t)b * ND * DS;

    // ================= forward =================
    {
        float Rprev = BIG2, upc = BIG2, upp = BIG2, prevB = BIG2;
        const int off = 64 * w;
        const int pstart = off >> 5, pend = (off + 366) >> 5;
        const float* bArow = bndA + w * W2 + PADJ;
        float* bAnext = bndA + (w + 1) * W2 + PADJ;
        for (int p = 0; p < 31; p++) {
            if (p >= pstart && p <= pend) {
                int s0 = p << 5;
                int j = s0 - off - l + 1;
                if (p == pstart && l == 0) prevB = bArow[0];
                float* gptr = gRb + (size_t)(s0 - 32 * w + 2) * DS + i;
                const float* oj = opack + (j - 1 + PADJ) * PSTR;
#pragma unroll 8
                for (int k = 0; k < 32; k++) {
                    bool act = row_ok && ((unsigned)(j - 1) < (unsigned)NN);
                    const float4 a = *(const float4*)(oj);
                    const float4 c = *(const float4*)(oj + 4);
                    float acc0 = tn2 + c.w;
                    acc0 = fmaf(-tL[0], a.x, acc0);
                    acc0 = fmaf(-tL[1], a.y, acc0);
                    acc0 = fmaf(-tL[2], a.z, acc0);
                    acc0 = fmaf(-tL[3], a.w, acc0);
                    acc0 = fmaf(-tL[4], c.x, acc0);
                    acc0 = fmaf(-tL[5], c.y, acc0);
                    acc0 = fmaf(-tL[6], c.z, acc0);
                    float D2 = fmaxf(acc0, 0.f);
                    float ru = upc, rd = upp, curB = 0.f;
                    if (l == 0) { curB = bArow[j]; ru = curB; rd = prevB; }
                    float rl = Rprev;
                    float lo = fminf(rd, ru), hi = fmaxf(rd, ru);
                    float m  = fminf(lo, rl);
                    float md = fmaxf(lo, fminf(hi, rl));
                    float Mx = fmaxf(hi, rl);
                    float z  = 1.f + ex2f(m - md) + ex2f(m - Mx);
                    float Rn = D2 + m - lg2f(z);
                    Rn = act ? Rn : BIG2;
                    if (act) {
                        *gptr = Rn;
                        if (l == 31 && w < NW - 1) bAnext[j] = Rn;
                    }
                    float sh = __shfl_up_sync(FULLM, Rn, 1);
                    upp = upc; upc = sh;
                    if (l == 0) prevB = curB;
                    Rprev = Rn;
                    j++; gptr += DS; oj += PSTR;
                }
            }
            __syncthreads();
        }
    }

    // re-init boundaries for backward: E = 0, s = NEGS
    for (int k = tid; k < NW * W2; k += TPB) { bndA[k] = 0.f; bndB[k] = NEGS; }
    __syncthreads();

    // ================= backward =================
    float tacc = 0.f;
    {
        float Eprev = 0.f, Sprev = NEGS;
        float Edn1  = 0.f, Sdn1  = NEGS;
        float Edn2  = 0.f, Sdn2  = NEGS;
        float rring[PF];
        const int off = 64 * (10 - w);
        const int pstart = off >> 5, pend = (off + 366) >> 5;
        const float* bArow = bndA + w * W2 + PADJ;
        const float* bBrow = bndB + w * W2 + PADJ;
        float* bAprev = bndA + (w - 1) * W2 + PADJ;
        float* bBprev = bndB + (w - 1) * W2 + PADJ;
        const bool seed_lane = (i == NN);
        for (int p = 0; p < 32; p++) {
            if (p >= pstart && p <= pend) {
                int s0 = p << 5;
                if (p == pstart) {
                    const float* pr = gRb + (size_t)(1008 - 32 * w - s0) * DS + i;
#pragma unroll
                    for (int q = 0; q < PF; q++) { rring[q] = *pr; pr -= DS; }
                }
                int j = 367 + off - s0 - l;
                float df = (float)(i - j);
                const float* ppf = gRb + (size_t)(1008 - 32 * w - s0 - PF) * DS + i;
                const float* oj = opack + (j - 1 + PADJ) * PSTR;
#pragma unroll 2
                for (int kb = 0; kb < 2; kb++) {
#pragma unroll
                    for (int kk = 0; kk < PF; kk++) {
                        bool act = row_ok && ((unsigned)(j - 1) < (unsigned)NN);
                        float Rij = rring[kk];
                        rring[kk] = *ppf; ppf -= DS;
                        if (l == 31) { Edn1 = bArow[j]; Sdn1 = bBrow[j]; }
                        const float4 a = *(const float4*)(oj);
                        const float4 c = *(const float4*)(oj + 4);
                        float acc0 = tn2 + c.w;
                        acc0 = fmaf(-tL[0], a.x, acc0);
                        acc0 = fmaf(-tL[1], a.y, acc0);
                        acc0 = fmaf(-tL[2], a.z, acc0);
                        acc0 = fmaf(-tL[3], a.w, acc0);
                        acc0 = fmaf(-tL[4], c.x, acc0);
                        acc0 = fmaf(-tL[5], c.y, acc0);
                        acc0 = fmaf(-tL[6], c.z, acc0);
                        float D2 = fmaxf(acc0, 0.f);
                        float w1 = ex2f(Sdn1 - Rij);
                        float w2 = ex2f(Sprev - Rij);
                        float w3 = ex2f(Sdn2 - Rij);
                        float En = fmaf(Edn1, w1, fmaf(Eprev, w2, Edn2 * w3));
                        if (seed_lane && j == NN) { En = 1.f; shape_s = Rij * LN2; }
                        float Sn = Rij - D2;
                        En = act ? En : 0.f;
                        Sn = act ? Sn : NEGS;
                        tacc = fmaf(En, df * df, tacc);
                        if (act && l == 0 && w > 0) { bAprev[j] = En; bBprev[j] = Sn; }
                        float Es = __shfl_down_sync(FULLM, En, 1);
                        float Ss = __shfl_down_sync(FULLM, Sn, 1);
                        Edn2 = Edn1; Sdn2 = Sdn1;
                        Edn1 = Es;   Sdn1 = Ss;
                        Eprev = En;  Sprev = Sn;
                        j--; df += 1.f; oj -= PSTR;
                    }
                }
            }
            __syncthreads();
        }
    }

    // ------- reduce temporal accumulator, finalize in last CTA -------
#pragma unroll
    for (int o2 = 16; o2; o2 >>= 1) tacc += __shfl_down_sync(FULLM, tacc, o2);
    if (l == 0) warpsum[w] = tacc;
    __syncthreads();
    if (tid == 0) {
        float sum = 0.f;
#pragma unroll
        for (int q = 0; q < NW; q++) sum += warpsum[q];
        atomicAdd(&g_temp_acc, (double)sum);
        atomicAdd(&g_shape_acc, (double)shape_s);
        __threadfence();
        unsigned old = atomicAdd(&g_done, 1u);
        if (old == NB - 1) {
            __threadfence();
            double shape    = g_shape_acc / (double)NB;
            double temporal = g_temp_acc / ((double)NN * NN * NB * NB);
            out[0] = (float)(0.5 * shape + 0.5 * temporal);
            g_shape_acc = 0.0;
            g_temp_acc  = 0.0;
            __threadfence();
            g_done = 0u;
        }
    }
}

extern "C" void kernel_launch(void* const* d_in, const int* in_sizes, int n_in,
                              void* d_out, int out_size) {
    const float* outputs = (const float*)d_in[0];
    const float* targets = (const float*)d_in[1];
    static int smem_set = 0;
    int smem_bytes = (NPTS * PSTR + 2 * NW * W2) * sizeof(float);   // 67328 B
    if (!smem_set) {
        cudaFuncSetAttribute(dilate_kernel, cudaFuncAttributeMaxDynamicSharedMemorySize,
                             smem_bytes);
        smem_set = 1;
    }
    dilate_kernel<<<NB, TPB, smem_bytes>>>(outputs, targets, (float*)d_out);
}